// round 12
// baseline (speedup 1.0000x reference)
#include <cuda_runtime.h>
#include <math.h>
#include <cstdint>

#define B_     64
#define N_     65
#define DIM_   128
#define HEADS_ 8
#define DH_    32
#define INNER_ 256
#define NM_    (N_*N_)                        // 4225
#define BH_    (B_*HEADS_)                    // 512

// ---------------- scratch (device globals; no allocation allowed) ----------
__device__ float g_xn[B_*N_*DIM_];            // layernormed x          [b][n][d]
__device__ float g_q [B_*HEADS_*N_*DH_];      // queries                [b][h][n][dh]
__device__ float g_k [B_*HEADS_*N_*DH_];      // keys                   [b][h][n][dh]
__device__ float g_attn_t[BH_*NM_];           // softmax weights        [bh][n][m]
__device__ float g_attn[NM_*BH_];             // transposed             [n][m][bh]
__device__ float g_vo[B_*N_*INNER_];          // attn-weighted v sums   [b][n][e]

// ---------------- helpers ---------------------------------------------------
__device__ __forceinline__ unsigned f2tf(float x) {
    unsigned r;
    asm("cvt.rna.tf32.f32 %0, %1;" : "=r"(r) : "f"(x));
    return r;
}

__device__ __forceinline__ void mma_tf32(float& c0, float& c1, float& c2, float& c3,
                                         unsigned a0, unsigned a1, unsigned a2, unsigned a3,
                                         unsigned b0, unsigned b1) {
    asm volatile(
        "mma.sync.aligned.m16n8k8.row.col.f32.tf32.tf32.f32 "
        "{%0,%1,%2,%3}, {%4,%5,%6,%7}, {%8,%9}, {%0,%1,%2,%3};\n"
        : "+f"(c0), "+f"(c1), "+f"(c2), "+f"(c3)
        : "r"(a0), "r"(a1), "r"(a2), "r"(a3), "r"(b0), "r"(b1));
}

__device__ __forceinline__ void cp16(void* smem_dst, const void* gsrc) {
    unsigned a = (unsigned)__cvta_generic_to_shared(smem_dst);
    asm volatile("cp.async.cg.shared.global [%0], [%1], 16;" :: "r"(a), "l"(gsrc));
}

// ---------------- Kernel 1: fused LayerNorm + QK projection -----------------
__global__ __launch_bounds__(256)
void qkln_kernel(const float* __restrict__ x,
                 const float* __restrict__ gamma,
                 const float* __restrict__ beta,
                 const float* __restrict__ Wqk) {
    __shared__ float xs[32][132];
    int blk  = blockIdx.x;        // 0..129
    int t    = threadIdx.x;       // 0..255
    int row0 = blk * 32;
    int w    = t >> 5, l = t & 31;

    float4 gm = *(const float4*)(gamma + l*4);
    float4 bt = *(const float4*)(beta  + l*4);

    #pragma unroll
    for (int rr = 0; rr < 4; rr++) {
        int r = w + rr*8;
        int grow = row0 + r;
        float4 v = *(const float4*)(x + (size_t)grow*DIM_ + l*4);
        float s  = v.x + v.y + v.z + v.w;
        float s2 = v.x*v.x + v.y*v.y + v.z*v.z + v.w*v.w;
        #pragma unroll
        for (int o = 16; o > 0; o >>= 1) {
            s  += __shfl_xor_sync(0xffffffffu, s,  o);
            s2 += __shfl_xor_sync(0xffffffffu, s2, o);
        }
        float mu   = s  * (1.0f/128.0f);
        float var  = s2 * (1.0f/128.0f) - mu*mu;
        float rstd = rsqrtf(var + 1e-5f);
        float4 xn;
        xn.x = (v.x - mu)*rstd*gm.x + bt.x;
        xn.y = (v.y - mu)*rstd*gm.y + bt.y;
        xn.z = (v.z - mu)*rstd*gm.z + bt.z;
        xn.w = (v.w - mu)*rstd*gm.w + bt.w;
        *(float4*)(&xs[r][l*4]) = xn;
        *(float4*)(g_xn + (size_t)grow*DIM_ + l*4) = xn;
    }
    __syncthreads();

    int eg = t & 63;
    int rg = t >> 6;
    int e0 = eg * 8;
    int r0 = rg * 8;

    float acc[8][8];
    #pragma unroll
    for (int r = 0; r < 8; r++)
        #pragma unroll
        for (int j = 0; j < 8; j++) acc[r][j] = 0.f;

    #pragma unroll 4
    for (int d = 0; d < 128; d++) {
        float4 w0 = *(const float4*)(Wqk + d*512 + e0);
        float4 w1 = *(const float4*)(Wqk + d*512 + e0 + 4);
        float wv[8] = {w0.x, w0.y, w0.z, w0.w, w1.x, w1.y, w1.z, w1.w};
        #pragma unroll
        for (int r = 0; r < 8; r++) {
            float xv = xs[r0 + r][d];
            #pragma unroll
            for (int j = 0; j < 8; j++) acc[r][j] += xv * wv[j];
        }
    }

    #pragma unroll
    for (int r = 0; r < 8; r++) {
        int grow = row0 + r0 + r;
        int b = grow / N_;
        int n = grow % N_;
        #pragma unroll
        for (int j = 0; j < 8; j++) {
            int e = e0 + j;
            if (e < 256) {
                int h = e >> 5, dh = e & 31;
                g_q[((b*HEADS_ + h)*N_ + n)*DH_ + dh] = acc[r][j];
            } else {
                int e2 = e - 256;
                int h = e2 >> 5, dh = e2 & 31;
                g_k[((b*HEADS_ + h)*N_ + n)*DH_ + dh] = acc[r][j];
            }
        }
    }
}

// ---------------- Kernel 2: scores + softmax, coalesced [bh][n][m] ----------
__global__ __launch_bounds__(256)
void attn_kernel() {
    int bh = blockIdx.x;                        // b*8 + h
    int t  = threadIdx.x;
    int warp = t >> 5, lane = t & 31;

    __shared__ float qs[N_][DH_+1];
    __shared__ float ks[N_][DH_+1];

    const float* qbase = g_q + (size_t)bh * N_ * DH_;
    const float* kbase = g_k + (size_t)bh * N_ * DH_;
    for (int i = t; i < N_*DH_; i += 256) {
        int n = i >> 5, d = i & 31;
        qs[n][d] = qbase[i];
        ks[n][d] = kbase[i];
    }
    __syncthreads();

    const float scale = 0.17677669529663687f;   // 32^-0.5

    for (int n = warp; n < N_; n += 8) {
        float s0 = 0.f, s1 = 0.f, s2 = 0.f;
        #pragma unroll
        for (int d = 0; d < DH_; d++) {
            float qv = qs[n][d];
            s0 += qv * ks[lane][d];
            s1 += qv * ks[lane+32][d];
            s2 += qv * ks[64][d];
        }
        s0 *= scale; s1 *= scale; s2 *= scale;
        float v2 = (lane == 0) ? s2 : -1e30f;
        float m = fmaxf(fmaxf(s0, s1), v2);
        #pragma unroll
        for (int o = 16; o > 0; o >>= 1)
            m = fmaxf(m, __shfl_xor_sync(0xffffffffu, m, o));
        float e0 = __expf(s0 - m);
        float e1 = __expf(s1 - m);
        float e2 = (lane == 0) ? __expf(s2 - m) : 0.f;
        float sm = e0 + e1 + e2;
        #pragma unroll
        for (int o = 16; o > 0; o >>= 1)
            sm += __shfl_xor_sync(0xffffffffu, sm, o);
        float inv = 1.0f / sm;

        float* wbase = g_attn_t + ((size_t)bh*N_ + n)*N_;   // contiguous in m
        wbase[lane]      = e0 * inv;
        wbase[lane + 32] = e1 * inv;
        if (lane == 0) wbase[64] = e2 * inv;
    }
}

// ---------------- Kernel 2b: transpose [bh][nm] -> [nm][bh] -----------------
__global__ __launch_bounds__(256)
void attn_tr_kernel() {
    __shared__ float tile[32][33];
    int nm0 = blockIdx.x * 32;
    int bh0 = blockIdx.y * 32;
    int tx = threadIdx.x & 31, ty = threadIdx.x >> 5;   // 32 x 8

    #pragma unroll
    for (int i = ty; i < 32; i += 8) {
        int nm = nm0 + tx;
        if (nm < NM_)
            tile[i][tx] = g_attn_t[(size_t)(bh0 + i)*NM_ + nm];
    }
    __syncthreads();
    #pragma unroll
    for (int i = ty; i < 32; i += 8) {
        int nm = nm0 + i;
        if (nm < NM_)
            g_attn[(size_t)nm*BH_ + bh0 + tx] = tile[tx][i];
    }
}

// ---------------- Kernel 3: per-(n,m) V GEMM + attn-weighted sum ------------
// grid (4, 65): blockIdx.x = 64-col quarter of INNER, blockIdx.y = n.
// Ring-3 pipeline of half-K (64-row x 64-col) Wv tiles, issue distance 2.
// 2 CTAs/SM (97 KB smem each) -> two independent pipelines hide latency.
// Warp tiling 2(M) x 4(N): warp = 32 rows x 16 cols (single head).
#define AS_STRIDE 132
#define BS_STRIDE 72
#define SMEM_A    (64*AS_STRIDE)               // 8448 words
#define SB_HALF   (64*BS_STRIDE)               // 4608 words per half-tile
#define NSTAGE    3
#define K3_SMEM_FLOATS (SMEM_A + NSTAGE*SB_HALF + 4*512)
#define K3_SMEM_BYTES  (K3_SMEM_FLOATS * 4)    // 97280 B

#define NHALF (2*N_)                           // 130 half-iterations

__global__ __launch_bounds__(256, 2)
void vattn_kernel(const float* __restrict__ Wv) {
    extern __shared__ float smem[];
    unsigned* A_s  = (unsigned*)smem;                 // [64][132] tf32 bits
    float*    B_s  = smem + SMEM_A;                   // [3][64][72] fp32
    float*    at_s = smem + SMEM_A + NSTAGE*SB_HALF;  // [4][512] attn slices

    int t    = threadIdx.x;
    int n    = blockIdx.y;
    int bx   = blockIdx.x;                            // 0..3 (64-col quarter)
    int warp = t >> 5, lane = t & 31;
    int gid  = lane >> 2, tig = lane & 3;
    int wm   = warp >> 2;                             // 0..1  (32 rows each)
    int wn   = warp & 3;                              // 0..3  (16 cols each)

    // A = xn[:, n, :] (64 x 128), rna tf32.
    {
        const float* xbase = g_xn + n*DIM_;
        #pragma unroll
        for (int i = 0; i < 8; i++) {
            int idx = t + i*256;
            int row = idx >> 5, c4 = idx & 31;
            float4 v = *(const float4*)(xbase + row*(N_*DIM_) + c4*4);
            unsigned* dst = A_s + row*AS_STRIDE + c4*4;
            dst[0] = f2tf(v.x); dst[1] = f2tf(v.y);
            dst[2] = f2tf(v.z); dst[3] = f2tf(v.w);
        }
    }

    const float* wv_n = Wv + (size_t)n * N_ * DIM_ * INNER_ + bx * 64;
    const float* at_n = g_attn + (size_t)n * N_ * BH_;

    // issue(j): fetch half-tile j (m = j>>1, k rows [(j&1)*64, +64), 64 cols)
    // into stage j%3; on even j also fetch attn slice for m into slot (j>>1)&3.
    auto issue = [&](int j) {
        int m = j >> 1;
        const float* src = wv_n + (size_t)m * DIM_ * INNER_
                                + (size_t)(j & 1) * 64 * INNER_;
        float* bd = B_s + (j % NSTAGE)*SB_HALF;
        #pragma unroll
        for (int i = 0; i < 4; i++) {
            int idx = t + i*256;                       // 0..1023 float4s
            int k = idx >> 4, c4 = idx & 15;
            cp16(bd + k*BS_STRIDE + c4*4, src + (size_t)k*INNER_ + c4*4);
        }
        if (!(j & 1) && t < 128)
            cp16(at_s + (m & 3)*512 + t*4, at_n + (size_t)m*512 + t*4);
        asm volatile("cp.async.commit_group;");
    };

    issue(0); issue(1);

    float o[2][2][4];
    #pragma unroll
    for (int tt = 0; tt < 2; tt++)
        #pragma unroll
        for (int nb = 0; nb < 2; nb++)
            #pragma unroll
            for (int j = 0; j < 4; j++) o[tt][nb][j] = 0.f;

    float c[2][2][4];
    int hb  = bx*2 + (wn >> 1);                 // single head for this warp
    int rb0 = wm*32;                            // first row of warp block

    for (int j = 0; j < NHALF; j++) {
        if (j < NHALF - 1) asm volatile("cp.async.wait_group 1;" ::: "memory");
        else               asm volatile("cp.async.wait_group 0;" ::: "memory");
        __syncthreads();
        if (j + 2 < NHALF) issue(j + 2);

        const float* bd = B_s + (j % NSTAGE)*SB_HALF;
        int koff = (j & 1) * 64;

        if (!(j & 1)) {
            #pragma unroll
            for (int tt = 0; tt < 2; tt++)
                #pragma unroll
                for (int nb = 0; nb < 2; nb++)
                    #pragma unroll
                    for (int q = 0; q < 4; q++) c[tt][nb][q] = 0.f;
        }

        #pragma unroll
        for (int kk = 0; kk < 8; kk++) {
            int k = kk*8;                              // local k within half
            unsigned a[2][4];
            #pragma unroll
            for (int tt = 0; tt < 2; tt++) {
                const unsigned* ar = A_s + (rb0 + tt*16 + gid)*AS_STRIDE + koff;
                a[tt][0] = ar[k + tig];
                a[tt][1] = ar[8*AS_STRIDE + k + tig];
                a[tt][2] = ar[k + tig + 4];
                a[tt][3] = ar[8*AS_STRIDE + k + tig + 4];
            }
            #pragma unroll
            for (int nb = 0; nb < 2; nb++) {
                int cb = wn*16 + nb*8 + gid;
                unsigned b0 = f2tf(bd[(k + tig    )*BS_STRIDE + cb]);
                unsigned b1 = f2tf(bd[(k + tig + 4)*BS_STRIDE + cb]);
                #pragma unroll
                for (int tt = 0; tt < 2; tt++)
                    mma_tf32(c[tt][nb][0], c[tt][nb][1], c[tt][nb][2], c[tt][nb][3],
                             a[tt][0], a[tt][1], a[tt][2], a[tt][3], b0, b1);
            }
        }

        if (j & 1) {                                   // m complete: scale + acc
            const float* at = at_s + ((j >> 1) & 3)*512;
            float a0r = at[(rb0 + gid     )*8 + hb];
            float a1r = at[(rb0 + gid +  8)*8 + hb];
            float a2r = at[(rb0 + gid + 16)*8 + hb];
            float a3r = at[(rb0 + gid + 24)*8 + hb];
            #pragma unroll
            for (int nb = 0; nb < 2; nb++) {
                o[0][nb][0] += a0r * c[0][nb][0];
                o[0][nb][1] += a0r * c[0][nb][1];
                o[0][nb][2] += a1r * c[0][nb][2];
                o[0][nb][3] += a1r * c[0][nb][3];
                o[1][nb][0] += a2r * c[1][nb][0];
                o[1][nb][1] += a2r * c[1][nb][1];
                o[1][nb][2] += a3r * c[1][nb][2];
                o[1][nb][3] += a3r * c[1][nb][3];
            }
        }
    }

    #pragma unroll
    for (int tt = 0; tt < 2; tt++) {
        int r = rb0 + tt*16 + gid;              // batch rows r, r+8
        #pragma unroll
        for (int nb = 0; nb < 2; nb++) {
            int col = bx*64 + wn*16 + nb*8 + tig*2;
            float* d1 = g_vo + ((size_t)r*N_ + n)*INNER_ + col;
            float* d2 = g_vo + ((size_t)(r+8)*N_ + n)*INNER_ + col;
            d1[0] = o[tt][nb][0]; d1[1] = o[tt][nb][1];
            d2[0] = o[tt][nb][2]; d2[1] = o[tt][nb][3];
        }
    }
}

// ---------------- Kernel 4: output projection, Wout resident in smem --------
#define K4_SMEM_BYTES ((256*128 + 32*256) * 4)   // 163840 B

__global__ __launch_bounds__(256, 1)
void out_kernel(const float* __restrict__ Wout,
                const float* __restrict__ bout,
                float* __restrict__ out) {
    extern __shared__ float4 sm4[];
    float4* wS = sm4;                 // [256][32]: e*32 + c4
    float4* vS = sm4 + 256*32;        // [32][64] : row*64 + e4

    int blk  = blockIdx.x;            // 0..129
    int t    = threadIdx.x;           // 0..255
    int row0 = blk * 32;

    const float4* W4 = (const float4*)Wout;
    #pragma unroll
    for (int i = t; i < 256*32; i += 256) wS[i] = W4[i];
    const float4* V4 = (const float4*)(g_vo + (size_t)row0*INNER_);
    #pragma unroll
    for (int i = t; i < 32*64; i += 256) vS[i] = V4[i];
    __syncthreads();

    int c4 = t & 31;                  // cols 4*c4 .. 4*c4+3
    int w  = t >> 5;                  // rows w, w+8, w+16, w+24
    float4 bo = ((const float4*)bout)[c4];
    float4 acc0 = bo, acc1 = bo, acc2 = bo, acc3 = bo;

    #pragma unroll 4
    for (int e4 = 0; e4 < 64; e4++) {
        float4 v0 = vS[(w     )*64 + e4];
        float4 v1 = vS[(w +  8)*64 + e4];
        float4 v2 = vS[(w + 16)*64 + e4];
        float4 v3 = vS[(w + 24)*64 + e4];
        #define OSTEP(KK, COMP)                                            \
        {   float4 wv = wS[(e4*4 + KK)*32 + c4];                           \
            acc0.x += v0.COMP*wv.x; acc0.y += v0.COMP*wv.y;                \
            acc0.z += v0.COMP*wv.z; acc0.w += v0.COMP*wv.w;                \
            acc1.x += v1.COMP*wv.x; acc1.y += v1.COMP*wv.y;                \
            acc1.z += v1.COMP*wv.z; acc1.w += v1.COMP*wv.w;                \
            acc2.x += v2.COMP*wv.x; acc2.y += v2.COMP*wv.y;                \
            acc2.z += v2.COMP*wv.z; acc2.w += v2.COMP*wv.w;                \
            acc3.x += v3.COMP*wv.x; acc3.y += v3.COMP*wv.y;                \
            acc3.z += v3.COMP*wv.z; acc3.w += v3.COMP*wv.w; }
        OSTEP(0, x) OSTEP(1, y) OSTEP(2, z) OSTEP(3, w)
        #undef OSTEP
    }

    ((float4*)(out + (size_t)(row0 + w     )*DIM_))[c4] = acc0;
    ((float4*)(out + (size_t)(row0 + w +  8)*DIM_))[c4] = acc1;
    ((float4*)(out + (size_t)(row0 + w + 16)*DIM_))[c4] = acc2;
    ((float4*)(out + (size_t)(row0 + w + 24)*DIM_))[c4] = acc3;
}

// ---------------- launch -----------------------------------------------------
extern "C" void kernel_launch(void* const* d_in, const int* in_sizes, int n_in,
                              void* d_out, int out_size) {
    const float* x     = (const float*)d_in[0];
    const float* gamma = (const float*)d_in[1];
    const float* beta  = (const float*)d_in[2];
    const float* Wqk   = (const float*)d_in[3];
    const float* Wv    = (const float*)d_in[4];
    const float* Wout  = (const float*)d_in[5];
    const float* bout  = (const float*)d_in[6];
    float* out = (float*)d_out;

    cudaFuncSetAttribute(vattn_kernel,
                         cudaFuncAttributeMaxDynamicSharedMemorySize,
                         K3_SMEM_BYTES);
    cudaFuncSetAttribute(out_kernel,
                         cudaFuncAttributeMaxDynamicSharedMemorySize,
                         K4_SMEM_BYTES);

    qkln_kernel<<<(B_*N_)/32, 256>>>(x, gamma, beta, Wqk);
    attn_kernel<<<B_*HEADS_, 256>>>();
    attn_tr_kernel<<<dim3((NM_ + 31)/32, BH_/32), 256>>>();
    dim3 g3(4, N_);
    vattn_kernel<<<g3, 256, K3_SMEM_BYTES>>>(Wv);
    out_kernel<<<(B_*N_)/32, 256, K4_SMEM_BYTES>>>(Wout, bout, out);
}

// round 13
// speedup vs baseline: 1.1406x; 1.1406x over previous
#include <cuda_runtime.h>
#include <math.h>
#include <cstdint>

#define B_     64
#define N_     65
#define DIM_   128
#define HEADS_ 8
#define DH_    32
#define INNER_ 256
#define NM_    (N_*N_)                        // 4225
#define BH_    (B_*HEADS_)                    // 512

// ---------------- scratch (device globals; no allocation allowed) ----------
__device__ float g_xn[B_*N_*DIM_];            // layernormed x          [b][n][d]
__device__ float g_q [B_*HEADS_*N_*DH_];      // queries                [b][h][n][dh]
__device__ float g_k [B_*HEADS_*N_*DH_];      // keys                   [b][h][n][dh]
__device__ float g_attn_t[BH_*NM_];           // softmax weights        [bh][n][m]
__device__ float g_attn[NM_*BH_];             // transposed             [n][m][bh]
__device__ float g_vo[B_*N_*INNER_];          // attn-weighted v sums   [b][n][e]

// ---------------- helpers ---------------------------------------------------
__device__ __forceinline__ unsigned f2tf(float x) {
    unsigned r;
    asm("cvt.rna.tf32.f32 %0, %1;" : "=r"(r) : "f"(x));
    return r;
}

__device__ __forceinline__ void mma_tf32(float& c0, float& c1, float& c2, float& c3,
                                         unsigned a0, unsigned a1, unsigned a2, unsigned a3,
                                         unsigned b0, unsigned b1) {
    asm volatile(
        "mma.sync.aligned.m16n8k8.row.col.f32.tf32.tf32.f32 "
        "{%0,%1,%2,%3}, {%4,%5,%6,%7}, {%8,%9}, {%0,%1,%2,%3};\n"
        : "+f"(c0), "+f"(c1), "+f"(c2), "+f"(c3)
        : "r"(a0), "r"(a1), "r"(a2), "r"(a3), "r"(b0), "r"(b1));
}

__device__ __forceinline__ void cp16(void* smem_dst, const void* gsrc) {
    unsigned a = (unsigned)__cvta_generic_to_shared(smem_dst);
    asm volatile("cp.async.cg.shared.global [%0], [%1], 16;" :: "r"(a), "l"(gsrc));
}

// ---------------- Kernel 1: fused LayerNorm + QK projection -----------------
__global__ __launch_bounds__(256)
void qkln_kernel(const float* __restrict__ x,
                 const float* __restrict__ gamma,
                 const float* __restrict__ beta,
                 const float* __restrict__ Wqk) {
    __shared__ float xs[32][132];
    int blk  = blockIdx.x;        // 0..129
    int t    = threadIdx.x;       // 0..255
    int row0 = blk * 32;
    int w    = t >> 5, l = t & 31;

    float4 gm = *(const float4*)(gamma + l*4);
    float4 bt = *(const float4*)(beta  + l*4);

    #pragma unroll
    for (int rr = 0; rr < 4; rr++) {
        int r = w + rr*8;
        int grow = row0 + r;
        float4 v = *(const float4*)(x + (size_t)grow*DIM_ + l*4);
        float s  = v.x + v.y + v.z + v.w;
        float s2 = v.x*v.x + v.y*v.y + v.z*v.z + v.w*v.w;
        #pragma unroll
        for (int o = 16; o > 0; o >>= 1) {
            s  += __shfl_xor_sync(0xffffffffu, s,  o);
            s2 += __shfl_xor_sync(0xffffffffu, s2, o);
        }
        float mu   = s  * (1.0f/128.0f);
        float var  = s2 * (1.0f/128.0f) - mu*mu;
        float rstd = rsqrtf(var + 1e-5f);
        float4 xn;
        xn.x = (v.x - mu)*rstd*gm.x + bt.x;
        xn.y = (v.y - mu)*rstd*gm.y + bt.y;
        xn.z = (v.z - mu)*rstd*gm.z + bt.z;
        xn.w = (v.w - mu)*rstd*gm.w + bt.w;
        *(float4*)(&xs[r][l*4]) = xn;
        *(float4*)(g_xn + (size_t)grow*DIM_ + l*4) = xn;
    }
    __syncthreads();

    int eg = t & 63;
    int rg = t >> 6;
    int e0 = eg * 8;
    int r0 = rg * 8;

    float acc[8][8];
    #pragma unroll
    for (int r = 0; r < 8; r++)
        #pragma unroll
        for (int j = 0; j < 8; j++) acc[r][j] = 0.f;

    #pragma unroll 4
    for (int d = 0; d < 128; d++) {
        float4 w0 = *(const float4*)(Wqk + d*512 + e0);
        float4 w1 = *(const float4*)(Wqk + d*512 + e0 + 4);
        float wv[8] = {w0.x, w0.y, w0.z, w0.w, w1.x, w1.y, w1.z, w1.w};
        #pragma unroll
        for (int r = 0; r < 8; r++) {
            float xv = xs[r0 + r][d];
            #pragma unroll
            for (int j = 0; j < 8; j++) acc[r][j] += xv * wv[j];
        }
    }

    #pragma unroll
    for (int r = 0; r < 8; r++) {
        int grow = row0 + r0 + r;
        int b = grow / N_;
        int n = grow % N_;
        #pragma unroll
        for (int j = 0; j < 8; j++) {
            int e = e0 + j;
            if (e < 256) {
                int h = e >> 5, dh = e & 31;
                g_q[((b*HEADS_ + h)*N_ + n)*DH_ + dh] = acc[r][j];
            } else {
                int e2 = e - 256;
                int h = e2 >> 5, dh = e2 & 31;
                g_k[((b*HEADS_ + h)*N_ + n)*DH_ + dh] = acc[r][j];
            }
        }
    }
}

// ---------------- Kernel 2: scores + softmax, coalesced [bh][n][m] ----------
__global__ __launch_bounds__(256)
void attn_kernel() {
    int bh = blockIdx.x;                        // b*8 + h
    int t  = threadIdx.x;
    int warp = t >> 5, lane = t & 31;

    __shared__ float qs[N_][DH_+1];
    __shared__ float ks[N_][DH_+1];

    const float* qbase = g_q + (size_t)bh * N_ * DH_;
    const float* kbase = g_k + (size_t)bh * N_ * DH_;
    for (int i = t; i < N_*DH_; i += 256) {
        int n = i >> 5, d = i & 31;
        qs[n][d] = qbase[i];
        ks[n][d] = kbase[i];
    }
    __syncthreads();

    const float scale = 0.17677669529663687f;   // 32^-0.5

    for (int n = warp; n < N_; n += 8) {
        float s0 = 0.f, s1 = 0.f, s2 = 0.f;
        #pragma unroll
        for (int d = 0; d < DH_; d++) {
            float qv = qs[n][d];
            s0 += qv * ks[lane][d];
            s1 += qv * ks[lane+32][d];
            s2 += qv * ks[64][d];
        }
        s0 *= scale; s1 *= scale; s2 *= scale;
        float v2 = (lane == 0) ? s2 : -1e30f;
        float m = fmaxf(fmaxf(s0, s1), v2);
        #pragma unroll
        for (int o = 16; o > 0; o >>= 1)
            m = fmaxf(m, __shfl_xor_sync(0xffffffffu, m, o));
        float e0 = __expf(s0 - m);
        float e1 = __expf(s1 - m);
        float e2 = (lane == 0) ? __expf(s2 - m) : 0.f;
        float sm = e0 + e1 + e2;
        #pragma unroll
        for (int o = 16; o > 0; o >>= 1)
            sm += __shfl_xor_sync(0xffffffffu, sm, o);
        float inv = 1.0f / sm;

        float* wbase = g_attn_t + ((size_t)bh*N_ + n)*N_;   // contiguous in m
        wbase[lane]      = e0 * inv;
        wbase[lane + 32] = e1 * inv;
        if (lane == 0) wbase[64] = e2 * inv;
    }
}

// ---------------- Kernel 2b: transpose [bh][nm] -> [nm][bh] -----------------
__global__ __launch_bounds__(256)
void attn_tr_kernel() {
    __shared__ float tile[32][33];
    int nm0 = blockIdx.x * 32;
    int bh0 = blockIdx.y * 32;
    int tx = threadIdx.x & 31, ty = threadIdx.x >> 5;   // 32 x 8

    #pragma unroll
    for (int i = ty; i < 32; i += 8) {
        int nm = nm0 + tx;
        if (nm < NM_)
            tile[i][tx] = g_attn_t[(size_t)(bh0 + i)*NM_ + nm];
    }
    __syncthreads();
    #pragma unroll
    for (int i = ty; i < 32; i += 8) {
        int nm = nm0 + i;
        if (nm < NM_)
            g_attn[(size_t)nm*BH_ + bh0 + tx] = tile[tx][i];
    }
}

// ---------------- Kernel 3: per-(n,m) V GEMM + attn-weighted sum ------------
// grid (2, 65). Ring-4 pipeline of half-K (64-row) Wv tiles, issue distance 3.
// A fragments (invariant across all m) hoisted into 128 registers: NO A-LDS
// in the main loop. Warp tiling 2(M) x 4(N).
#define AS_STRIDE 132
#define BS_STRIDE 136
#define SMEM_A    (64*AS_STRIDE)               // 8448 words
#define SB_HALF   (64*BS_STRIDE)               // 8704 words per half-tile
#define NSTAGE    4
#define K3_SMEM_FLOATS (SMEM_A + NSTAGE*SB_HALF + 4*512)
#define K3_SMEM_BYTES  (K3_SMEM_FLOATS * 4)    // 181248 B

#define NHALF (2*N_)                           // 130 half-iterations

__global__ __launch_bounds__(256, 1)
void vattn_kernel(const float* __restrict__ Wv) {
    extern __shared__ float smem[];
    unsigned* A_s  = (unsigned*)smem;                 // [64][132] tf32 bits
    float*    B_s  = smem + SMEM_A;                   // [4][64][136] fp32
    float*    at_s = smem + SMEM_A + NSTAGE*SB_HALF;  // [4][512] attn slices

    int t    = threadIdx.x;
    int n    = blockIdx.y;
    int bx   = blockIdx.x;
    int warp = t >> 5, lane = t & 31;
    int gid  = lane >> 2, tig = lane & 3;
    int wm   = warp >> 2;                             // 0..1  (32 rows each)
    int wn   = warp & 3;                              // 0..3  (32 cols each)

    // Stage A = xn[:, n, :] (64 x 128) into smem with rna tf32 conversion.
    {
        const float* xbase = g_xn + n*DIM_;
        #pragma unroll
        for (int i = 0; i < 8; i++) {
            int idx = t + i*256;
            int row = idx >> 5, c4 = idx & 31;
            float4 v = *(const float4*)(xbase + row*(N_*DIM_) + c4*4);
            unsigned* dst = A_s + row*AS_STRIDE + c4*4;
            dst[0] = f2tf(v.x); dst[1] = f2tf(v.y);
            dst[2] = f2tf(v.z); dst[3] = f2tf(v.w);
        }
    }

    const float* wv_n = Wv + (size_t)n * N_ * DIM_ * INNER_ + bx * 128;
    const float* at_n = g_attn + (size_t)n * N_ * BH_;

    // issue(j): fetch half-tile j (m = j>>1, k rows [(j&1)*64, +64)) into
    // stage j%4; on even j also fetch attn slice for m into slot (j>>1)&3.
    auto issue = [&](int j) {
        int m = j >> 1;
        const float* src = wv_n + (size_t)m * DIM_ * INNER_
                                + (size_t)(j & 1) * 64 * INNER_;
        float* bd = B_s + (j & 3)*SB_HALF;
        #pragma unroll
        for (int i = 0; i < 8; i++) {
            int idx = t + i*256;                       // 0..2047 float4s
            int k = idx >> 5, c4 = idx & 31;
            cp16(bd + k*BS_STRIDE + c4*4, src + (size_t)k*INNER_ + c4*4);
        }
        if (!(j & 1) && t < 128)
            cp16(at_s + (m & 3)*512 + t*4, at_n + (size_t)m*512 + t*4);
        asm volatile("cp.async.commit_group;");
    };

    int rb0 = wm*32;                            // first row of warp block
    int hb  = bx*4 + wn;                        // single head for this warp

    __syncthreads();                            // A_s writes visible

    // Hoist ALL A fragments into registers (invariant over m).
    unsigned ar[2][16][4];
    #pragma unroll
    for (int tt = 0; tt < 2; tt++) {
        const unsigned* a0p = A_s + (rb0 + tt*16 + gid)*AS_STRIDE;
        const unsigned* a1p = a0p + 8*AS_STRIDE;
        #pragma unroll
        for (int kk = 0; kk < 16; kk++) {
            ar[tt][kk][0] = a0p[kk*8 + tig];
            ar[tt][kk][1] = a1p[kk*8 + tig];
            ar[tt][kk][2] = a0p[kk*8 + tig + 4];
            ar[tt][kk][3] = a1p[kk*8 + tig + 4];
        }
    }

    issue(0); issue(1); issue(2);

    float o[2][4][4];
    #pragma unroll
    for (int tt = 0; tt < 2; tt++)
        #pragma unroll
        for (int nb = 0; nb < 4; nb++)
            #pragma unroll
            for (int j = 0; j < 4; j++) o[tt][nb][j] = 0.f;

    float c[2][4][4];

    // pipestep: wait/sync/issue for half-iter j
    auto pipestep = [&](int j) {
        int rem = (NHALF - 1) - j;
        if (rem >= 2)      asm volatile("cp.async.wait_group 2;" ::: "memory");
        else if (rem == 1) asm volatile("cp.async.wait_group 1;" ::: "memory");
        else               asm volatile("cp.async.wait_group 0;" ::: "memory");
        __syncthreads();
        if (j + 3 < NHALF) issue(j + 3);
    };

    // COMPUTE over 8 kk steps with literal k-base KB (A regs statically indexed)
    #define COMPUTE(BD, KB)                                                   \
    {                                                                         \
        _Pragma("unroll")                                                     \
        for (int kk = 0; kk < 8; kk++) {                                      \
            int k = kk*8;                                                     \
            _Pragma("unroll")                                                 \
            for (int nb = 0; nb < 4; nb++) {                                  \
                int cb = wn*32 + nb*8 + gid;                                  \
                unsigned b0 = f2tf((BD)[(k + tig    )*BS_STRIDE + cb]);       \
                unsigned b1 = f2tf((BD)[(k + tig + 4)*BS_STRIDE + cb]);       \
                mma_tf32(c[0][nb][0], c[0][nb][1], c[0][nb][2], c[0][nb][3],  \
                         ar[0][KB+kk][0], ar[0][KB+kk][1],                    \
                         ar[0][KB+kk][2], ar[0][KB+kk][3], b0, b1);           \
                mma_tf32(c[1][nb][0], c[1][nb][1], c[1][nb][2], c[1][nb][3],  \
                         ar[1][KB+kk][0], ar[1][KB+kk][1],                    \
                         ar[1][KB+kk][2], ar[1][KB+kk][3], b0, b1);           \
            }                                                                 \
        }                                                                     \
    }

    for (int m = 0; m < N_; m++) {
        int j0 = 2*m;

        pipestep(j0);
        const float* bd0 = B_s + (j0 & 3)*SB_HALF;
        #pragma unroll
        for (int tt = 0; tt < 2; tt++)
            #pragma unroll
            for (int nb = 0; nb < 4; nb++)
                #pragma unroll
                for (int q = 0; q < 4; q++) c[tt][nb][q] = 0.f;
        COMPUTE(bd0, 0)

        pipestep(j0 + 1);
        const float* bd1 = B_s + ((j0 + 1) & 3)*SB_HALF;
        COMPUTE(bd1, 8)

        const float* at = at_s + (m & 3)*512;
        float a0r = at[(rb0 + gid     )*8 + hb];
        float a1r = at[(rb0 + gid +  8)*8 + hb];
        float a2r = at[(rb0 + gid + 16)*8 + hb];
        float a3r = at[(rb0 + gid + 24)*8 + hb];
        #pragma unroll
        for (int nb = 0; nb < 4; nb++) {
            o[0][nb][0] += a0r * c[0][nb][0];
            o[0][nb][1] += a0r * c[0][nb][1];
            o[0][nb][2] += a1r * c[0][nb][2];
            o[0][nb][3] += a1r * c[0][nb][3];
            o[1][nb][0] += a2r * c[1][nb][0];
            o[1][nb][1] += a2r * c[1][nb][1];
            o[1][nb][2] += a3r * c[1][nb][2];
            o[1][nb][3] += a3r * c[1][nb][3];
        }
    }
    #undef COMPUTE

    #pragma unroll
    for (int tt = 0; tt < 2; tt++) {
        int r = rb0 + tt*16 + gid;              // batch rows r, r+8
        #pragma unroll
        for (int nb = 0; nb < 4; nb++) {
            int col = bx*128 + wn*32 + nb*8 + tig*2;
            float* d1 = g_vo + ((size_t)r*N_ + n)*INNER_ + col;
            float* d2 = g_vo + ((size_t)(r+8)*N_ + n)*INNER_ + col;
            d1[0] = o[tt][nb][0]; d1[1] = o[tt][nb][1];
            d2[0] = o[tt][nb][2]; d2[1] = o[tt][nb][3];
        }
    }
}

// ---------------- Kernel 4: output projection, Wout resident in smem --------
#define K4_SMEM_BYTES ((256*128 + 32*256) * 4)   // 163840 B

__global__ __launch_bounds__(256, 1)
void out_kernel(const float* __restrict__ Wout,
                const float* __restrict__ bout,
                float* __restrict__ out) {
    extern __shared__ float4 sm4[];
    float4* wS = sm4;                 // [256][32]: e*32 + c4
    float4* vS = sm4 + 256*32;        // [32][64] : row*64 + e4

    int blk  = blockIdx.x;            // 0..129
    int t    = threadIdx.x;           // 0..255
    int row0 = blk * 32;

    const float4* W4 = (const float4*)Wout;
    #pragma unroll
    for (int i = t; i < 256*32; i += 256) wS[i] = W4[i];
    const float4* V4 = (const float4*)(g_vo + (size_t)row0*INNER_);
    #pragma unroll
    for (int i = t; i < 32*64; i += 256) vS[i] = V4[i];
    __syncthreads();

    int c4 = t & 31;                  // cols 4*c4 .. 4*c4+3
    int w  = t >> 5;                  // rows w, w+8, w+16, w+24
    float4 bo = ((const float4*)bout)[c4];
    float4 acc0 = bo, acc1 = bo, acc2 = bo, acc3 = bo;

    #pragma unroll 4
    for (int e4 = 0; e4 < 64; e4++) {
        float4 v0 = vS[(w     )*64 + e4];
        float4 v1 = vS[(w +  8)*64 + e4];
        float4 v2 = vS[(w + 16)*64 + e4];
        float4 v3 = vS[(w + 24)*64 + e4];
        #define OSTEP(KK, COMP)                                            \
        {   float4 wv = wS[(e4*4 + KK)*32 + c4];                           \
            acc0.x += v0.COMP*wv.x; acc0.y += v0.COMP*wv.y;                \
            acc0.z += v0.COMP*wv.z; acc0.w += v0.COMP*wv.w;                \
            acc1.x += v1.COMP*wv.x; acc1.y += v1.COMP*wv.y;                \
            acc1.z += v1.COMP*wv.z; acc1.w += v1.COMP*wv.w;                \
            acc2.x += v2.COMP*wv.x; acc2.y += v2.COMP*wv.y;                \
            acc2.z += v2.COMP*wv.z; acc2.w += v2.COMP*wv.w;                \
            acc3.x += v3.COMP*wv.x; acc3.y += v3.COMP*wv.y;                \
            acc3.z += v3.COMP*wv.z; acc3.w += v3.COMP*wv.w; }
        OSTEP(0, x) OSTEP(1, y) OSTEP(2, z) OSTEP(3, w)
        #undef OSTEP
    }

    ((float4*)(out + (size_t)(row0 + w     )*DIM_))[c4] = acc0;
    ((float4*)(out + (size_t)(row0 + w +  8)*DIM_))[c4] = acc1;
    ((float4*)(out + (size_t)(row0 + w + 16)*DIM_))[c4] = acc2;
    ((float4*)(out + (size_t)(row0 + w + 24)*DIM_))[c4] = acc3;
}

// ---------------- launch -----------------------------------------------------
extern "C" void kernel_launch(void* const* d_in, const int* in_sizes, int n_in,
                              void* d_out, int out_size) {
    const float* x     = (const float*)d_in[0];
    const float* gamma = (const float*)d_in[1];
    const float* beta  = (const float*)d_in[2];
    const float* Wqk   = (const float*)d_in[3];
    const float* Wv    = (const float*)d_in[4];
    const float* Wout  = (const float*)d_in[5];
    const float* bout  = (const float*)d_in[6];
    float* out = (float*)d_out;

    cudaFuncSetAttribute(vattn_kernel,
                         cudaFuncAttributeMaxDynamicSharedMemorySize,
                         K3_SMEM_BYTES);
    cudaFuncSetAttribute(out_kernel,
                         cudaFuncAttributeMaxDynamicSharedMemorySize,
                         K4_SMEM_BYTES);

    qkln_kernel<<<(B_*N_)/32, 256>>>(x, gamma, beta, Wqk);
    attn_kernel<<<B_*HEADS_, 256>>>();
    attn_tr_kernel<<<dim3((NM_ + 31)/32, BH_/32), 256>>>();
    dim3 g3(2, N_);
    vattn_kernel<<<g3, 256, K3_SMEM_BYTES>>>(Wv);
    out_kernel<<<(B_*N_)/32, 256, K4_SMEM_BYTES>>>(Wout, bout, out);
}

// round 16
// speedup vs baseline: 1.2351x; 1.0828x over previous
#include <cuda_runtime.h>
#include <math.h>
#include <cstdint>

#define B_     64
#define N_     65
#define DIM_   128
#define HEADS_ 8
#define DH_    32
#define INNER_ 256
#define NM_    (N_*N_)                        // 4225
#define BH_    (B_*HEADS_)                    // 512

// ---------------- scratch (device globals; no allocation allowed) ----------
__device__ float g_xn[B_*N_*DIM_];            // layernormed x          [b][n][d]
__device__ float g_q [B_*HEADS_*N_*DH_];      // queries                [b][h][n][dh]
__device__ float g_k [B_*HEADS_*N_*DH_];      // keys                   [b][h][n][dh]
__device__ float g_attn_t[BH_*NM_];           // softmax weights        [bh][n][m]
__device__ float g_attn[NM_*BH_];             // transposed             [n][m][bh]
__device__ float g_vo[B_*N_*INNER_];          // attn-weighted v sums   [b][n][e]

// ---------------- helpers ---------------------------------------------------
__device__ __forceinline__ unsigned f2tf(float x) {
    unsigned r;
    asm("cvt.rna.tf32.f32 %0, %1;" : "=r"(r) : "f"(x));
    return r;
}

__device__ __forceinline__ void mma_tf32(float& c0, float& c1, float& c2, float& c3,
                                         unsigned a0, unsigned a1, unsigned a2, unsigned a3,
                                         unsigned b0, unsigned b1) {
    asm volatile(
        "mma.sync.aligned.m16n8k8.row.col.f32.tf32.tf32.f32 "
        "{%0,%1,%2,%3}, {%4,%5,%6,%7}, {%8,%9}, {%0,%1,%2,%3};\n"
        : "+f"(c0), "+f"(c1), "+f"(c2), "+f"(c3)
        : "r"(a0), "r"(a1), "r"(a2), "r"(a3), "r"(b0), "r"(b1));
}

__device__ __forceinline__ void cp16(void* smem_dst, const void* gsrc) {
    unsigned a = (unsigned)__cvta_generic_to_shared(smem_dst);
    asm volatile("cp.async.cg.shared.global [%0], [%1], 16;" :: "r"(a), "l"(gsrc));
}

// ---------------- Kernel 1: fused LayerNorm + QK projection -----------------
__global__ __launch_bounds__(256)
void qkln_kernel(const float* __restrict__ x,
                 const float* __restrict__ gamma,
                 const float* __restrict__ beta,
                 const float* __restrict__ Wqk) {
    __shared__ float xs[32][132];
    int blk  = blockIdx.x;        // 0..129
    int t    = threadIdx.x;       // 0..255
    int row0 = blk * 32;
    int w    = t >> 5, l = t & 31;

    float4 gm = *(const float4*)(gamma + l*4);
    float4 bt = *(const float4*)(beta  + l*4);

    #pragma unroll
    for (int rr = 0; rr < 4; rr++) {
        int r = w + rr*8;
        int grow = row0 + r;
        float4 v = *(const float4*)(x + (size_t)grow*DIM_ + l*4);
        float s  = v.x + v.y + v.z + v.w;
        float s2 = v.x*v.x + v.y*v.y + v.z*v.z + v.w*v.w;
        #pragma unroll
        for (int o = 16; o > 0; o >>= 1) {
            s  += __shfl_xor_sync(0xffffffffu, s,  o);
            s2 += __shfl_xor_sync(0xffffffffu, s2, o);
        }
        float mu   = s  * (1.0f/128.0f);
        float var  = s2 * (1.0f/128.0f) - mu*mu;
        float rstd = rsqrtf(var + 1e-5f);
        float4 xn;
        xn.x = (v.x - mu)*rstd*gm.x + bt.x;
        xn.y = (v.y - mu)*rstd*gm.y + bt.y;
        xn.z = (v.z - mu)*rstd*gm.z + bt.z;
        xn.w = (v.w - mu)*rstd*gm.w + bt.w;
        *(float4*)(&xs[r][l*4]) = xn;
        *(float4*)(g_xn + (size_t)grow*DIM_ + l*4) = xn;
    }
    __syncthreads();

    int eg = t & 63;
    int rg = t >> 6;
    int e0 = eg * 8;
    int r0 = rg * 8;

    float acc[8][8];
    #pragma unroll
    for (int r = 0; r < 8; r++)
        #pragma unroll
        for (int j = 0; j < 8; j++) acc[r][j] = 0.f;

    #pragma unroll 4
    for (int d = 0; d < 128; d++) {
        float4 w0 = *(const float4*)(Wqk + d*512 + e0);
        float4 w1 = *(const float4*)(Wqk + d*512 + e0 + 4);
        float wv[8] = {w0.x, w0.y, w0.z, w0.w, w1.x, w1.y, w1.z, w1.w};
        #pragma unroll
        for (int r = 0; r < 8; r++) {
            float xv = xs[r0 + r][d];
            #pragma unroll
            for (int j = 0; j < 8; j++) acc[r][j] += xv * wv[j];
        }
    }

    #pragma unroll
    for (int r = 0; r < 8; r++) {
        int grow = row0 + r0 + r;
        int b = grow / N_;
        int n = grow % N_;
        #pragma unroll
        for (int j = 0; j < 8; j++) {
            int e = e0 + j;
            if (e < 256) {
                int h = e >> 5, dh = e & 31;
                g_q[((b*HEADS_ + h)*N_ + n)*DH_ + dh] = acc[r][j];
            } else {
                int e2 = e - 256;
                int h = e2 >> 5, dh = e2 & 31;
                g_k[((b*HEADS_ + h)*N_ + n)*DH_ + dh] = acc[r][j];
            }
        }
    }
}

// ---------------- Kernel 2: scores + softmax, coalesced [bh][n][m] ----------
__global__ __launch_bounds__(256)
void attn_kernel() {
    int bh = blockIdx.x;                        // b*8 + h
    int t  = threadIdx.x;
    int warp = t >> 5, lane = t & 31;

    __shared__ float qs[N_][DH_+1];
    __shared__ float ks[N_][DH_+1];

    const float* qbase = g_q + (size_t)bh * N_ * DH_;
    const float* kbase = g_k + (size_t)bh * N_ * DH_;
    for (int i = t; i < N_*DH_; i += 256) {
        int n = i >> 5, d = i & 31;
        qs[n][d] = qbase[i];
        ks[n][d] = kbase[i];
    }
    __syncthreads();

    const float scale = 0.17677669529663687f;   // 32^-0.5

    for (int n = warp; n < N_; n += 8) {
        float s0 = 0.f, s1 = 0.f, s2 = 0.f;
        #pragma unroll
        for (int d = 0; d < DH_; d++) {
            float qv = qs[n][d];
            s0 += qv * ks[lane][d];
            s1 += qv * ks[lane+32][d];
            s2 += qv * ks[64][d];
        }
        s0 *= scale; s1 *= scale; s2 *= scale;
        float v2 = (lane == 0) ? s2 : -1e30f;
        float m = fmaxf(fmaxf(s0, s1), v2);
        #pragma unroll
        for (int o = 16; o > 0; o >>= 1)
            m = fmaxf(m, __shfl_xor_sync(0xffffffffu, m, o));
        float e0 = __expf(s0 - m);
        float e1 = __expf(s1 - m);
        float e2 = (lane == 0) ? __expf(s2 - m) : 0.f;
        float sm = e0 + e1 + e2;
        #pragma unroll
        for (int o = 16; o > 0; o >>= 1)
            sm += __shfl_xor_sync(0xffffffffu, sm, o);
        float inv = 1.0f / sm;

        float* wbase = g_attn_t + ((size_t)bh*N_ + n)*N_;   // contiguous in m
        wbase[lane]      = e0 * inv;
        wbase[lane + 32] = e1 * inv;
        if (lane == 0) wbase[64] = e2 * inv;
    }
}

// ---------------- Kernel 2b: transpose [bh][nm] -> [nm][bh] -----------------
__global__ __launch_bounds__(256)
void attn_tr_kernel() {
    __shared__ float tile[32][33];
    int nm0 = blockIdx.x * 32;
    int bh0 = blockIdx.y * 32;
    int tx = threadIdx.x & 31, ty = threadIdx.x >> 5;   // 32 x 8

    #pragma unroll
    for (int i = ty; i < 32; i += 8) {
        int nm = nm0 + tx;
        if (nm < NM_)
            tile[i][tx] = g_attn_t[(size_t)(bh0 + i)*NM_ + nm];
    }
    __syncthreads();
    #pragma unroll
    for (int i = ty; i < 32; i += 8) {
        int nm = nm0 + i;
        if (nm < NM_)
            g_attn[(size_t)nm*BH_ + bh0 + tx] = tile[tx][i];
    }
}

// ---------------- Kernel 3: per-(n,m) V GEMM + attn-weighted sum ------------
// grid (2, 65). Ring-4 pipeline of half-K (64-row) Wv tiles, issue distance 3.
// A fragments (invariant across all m) hoisted into 128 registers (rna tf32);
// B fragments fed to mma.tf32 as RAW fp32 bits (HW truncates to tf32) — no
// per-fragment cvt in the loop. Warp tiling 2(M) x 4(N).
#define AS_STRIDE 132
#define BS_STRIDE 136
#define SMEM_A    (64*AS_STRIDE)               // 8448 words
#define SB_HALF   (64*BS_STRIDE)               // 8704 words per half-tile
#define NSTAGE    4
#define K3_SMEM_FLOATS (SMEM_A + NSTAGE*SB_HALF + 4*512)
#define K3_SMEM_BYTES  (K3_SMEM_FLOATS * 4)    // 181248 B

#define NHALF (2*N_)                           // 130 half-iterations

__global__ __launch_bounds__(256, 1)
void vattn_kernel(const float* __restrict__ Wv) {
    extern __shared__ float smem[];
    unsigned* A_s  = (unsigned*)smem;                 // [64][132] tf32 bits
    float*    B_s  = smem + SMEM_A;                   // [4][64][136] fp32
    float*    at_s = smem + SMEM_A + NSTAGE*SB_HALF;  // [4][512] attn slices

    int t    = threadIdx.x;
    int n    = blockIdx.y;
    int bx   = blockIdx.x;
    int warp = t >> 5, lane = t & 31;
    int gid  = lane >> 2, tig = lane & 3;
    int wm   = warp >> 2;                             // 0..1  (32 rows each)
    int wn   = warp & 3;                              // 0..3  (32 cols each)

    // Stage A = xn[:, n, :] (64 x 128) into smem with rna tf32 conversion.
    {
        const float* xbase = g_xn + n*DIM_;
        #pragma unroll
        for (int i = 0; i < 8; i++) {
            int idx = t + i*256;
            int row = idx >> 5, c4 = idx & 31;
            float4 v = *(const float4*)(xbase + row*(N_*DIM_) + c4*4);
            unsigned* dst = A_s + row*AS_STRIDE + c4*4;
            dst[0] = f2tf(v.x); dst[1] = f2tf(v.y);
            dst[2] = f2tf(v.z); dst[3] = f2tf(v.w);
        }
    }

    const float* wv_n = Wv + (size_t)n * N_ * DIM_ * INNER_ + bx * 128;
    const float* at_n = g_attn + (size_t)n * N_ * BH_;

    // issue(j): fetch half-tile j (m = j>>1, k rows [(j&1)*64, +64)) into
    // stage j%4; on even j also fetch attn slice for m into slot (j>>1)&3.
    auto issue = [&](int j) {
        int m = j >> 1;
        const float* src = wv_n + (size_t)m * DIM_ * INNER_
                                + (size_t)(j & 1) * 64 * INNER_;
        float* bd = B_s + (j & 3)*SB_HALF;
        #pragma unroll
        for (int i = 0; i < 8; i++) {
            int idx = t + i*256;                       // 0..2047 float4s
            int k = idx >> 5, c4 = idx & 31;
            cp16(bd + k*BS_STRIDE + c4*4, src + (size_t)k*INNER_ + c4*4);
        }
        if (!(j & 1) && t < 128)
            cp16(at_s + (m & 3)*512 + t*4, at_n + (size_t)m*512 + t*4);
        asm volatile("cp.async.commit_group;");
    };

    int rb0 = wm*32;                            // first row of warp block
    int hb  = bx*4 + wn;                        // single head for this warp

    __syncthreads();                            // A_s writes visible

    // Hoist ALL A fragments into registers (invariant over m).
    unsigned ar[2][16][4];
    #pragma unroll
    for (int tt = 0; tt < 2; tt++) {
        const unsigned* a0p = A_s + (rb0 + tt*16 + gid)*AS_STRIDE;
        const unsigned* a1p = a0p + 8*AS_STRIDE;
        #pragma unroll
        for (int kk = 0; kk < 16; kk++) {
            ar[tt][kk][0] = a0p[kk*8 + tig];
            ar[tt][kk][1] = a1p[kk*8 + tig];
            ar[tt][kk][2] = a0p[kk*8 + tig + 4];
            ar[tt][kk][3] = a1p[kk*8 + tig + 4];
        }
    }

    issue(0); issue(1); issue(2);

    float o[2][4][4];
    #pragma unroll
    for (int tt = 0; tt < 2; tt++)
        #pragma unroll
        for (int nb = 0; nb < 4; nb++)
            #pragma unroll
            for (int j = 0; j < 4; j++) o[tt][nb][j] = 0.f;

    float c[2][4][4];

    // pipestep: wait/sync/issue for half-iter j
    auto pipestep = [&](int j) {
        int rem = (NHALF - 1) - j;
        if (rem >= 2)      asm volatile("cp.async.wait_group 2;" ::: "memory");
        else if (rem == 1) asm volatile("cp.async.wait_group 1;" ::: "memory");
        else               asm volatile("cp.async.wait_group 0;" ::: "memory");
        __syncthreads();
        if (j + 3 < NHALF) issue(j + 3);
    };

    // COMPUTE over 8 kk steps with literal k-base KB; B fragments are RAW fp32
    // bits straight from smem (tensor core truncates to tf32 internally).
    #define COMPUTE(BD, KB)                                                   \
    {                                                                         \
        const unsigned* bdu = (const unsigned*)(BD);                          \
        _Pragma("unroll")                                                     \
        for (int kk = 0; kk < 8; kk++) {                                      \
            int k = kk*8;                                                     \
            _Pragma("unroll")                                                 \
            for (int nb = 0; nb < 4; nb++) {                                  \
                int cb = wn*32 + nb*8 + gid;                                  \
                unsigned b0 = bdu[(k + tig    )*BS_STRIDE + cb];              \
                unsigned b1 = bdu[(k + tig + 4)*BS_STRIDE + cb];              \
                mma_tf32(c[0][nb][0], c[0][nb][1], c[0][nb][2], c[0][nb][3],  \
                         ar[0][KB+kk][0], ar[0][KB+kk][1],                    \
                         ar[0][KB+kk][2], ar[0][KB+kk][3], b0, b1);           \
                mma_tf32(c[1][nb][0], c[1][nb][1], c[1][nb][2], c[1][nb][3],  \
                         ar[1][KB+kk][0], ar[1][KB+kk][1],                    \
                         ar[1][KB+kk][2], ar[1][KB+kk][3], b0, b1);           \
            }                                                                 \
        }                                                                     \
    }

    for (int m = 0; m < N_; m++) {
        int j0 = 2*m;

        pipestep(j0);
        // attn factors for this m arrived with the even half-tile: load early
        // so the LDS completes under the MMAs.
        const float* at = at_s + (m & 3)*512;
        float a0r = at[(rb0 + gid     )*8 + hb];
        float a1r = at[(rb0 + gid +  8)*8 + hb];
        float a2r = at[(rb0 + gid + 16)*8 + hb];
        float a3r = at[(rb0 + gid + 24)*8 + hb];

        const float* bd0 = B_s + (j0 & 3)*SB_HALF;
        #pragma unroll
        for (int tt = 0; tt < 2; tt++)
            #pragma unroll
            for (int nb = 0; nb < 4; nb++)
                #pragma unroll
                for (int q = 0; q < 4; q++) c[tt][nb][q] = 0.f;
        COMPUTE(bd0, 0)

        pipestep(j0 + 1);
        const float* bd1 = B_s + ((j0 + 1) & 3)*SB_HALF;
        COMPUTE(bd1, 8)

        #pragma unroll
        for (int nb = 0; nb < 4; nb++) {
            o[0][nb][0] += a0r * c[0][nb][0];
            o[0][nb][1] += a0r * c[0][nb][1];
            o[0][nb][2] += a1r * c[0][nb][2];
            o[0][nb][3] += a1r * c[0][nb][3];
            o[1][nb][0] += a2r * c[1][nb][0];
            o[1][nb][1] += a2r * c[1][nb][1];
            o[1][nb][2] += a3r * c[1][nb][2];
            o[1][nb][3] += a3r * c[1][nb][3];
        }
    }
    #undef COMPUTE

    #pragma unroll
    for (int tt = 0; tt < 2; tt++) {
        int r = rb0 + tt*16 + gid;              // batch rows r, r+8
        #pragma unroll
        for (int nb = 0; nb < 4; nb++) {
            int col = bx*128 + wn*32 + nb*8 + tig*2;
            float* d1 = g_vo + ((size_t)r*N_ + n)*INNER_ + col;
            float* d2 = g_vo + ((size_t)(r+8)*N_ + n)*INNER_ + col;
            d1[0] = o[tt][nb][0]; d1[1] = o[tt][nb][1];
            d2[0] = o[tt][nb][2]; d2[1] = o[tt][nb][3];
        }
    }
}

// ---------------- Kernel 4: output projection, Wout resident in smem --------
#define K4_SMEM_BYTES ((256*128 + 32*256) * 4)   // 163840 B

__global__ __launch_bounds__(256, 1)
void out_kernel(const float* __restrict__ Wout,
                const float* __restrict__ bout,
                float* __restrict__ out) {
    extern __shared__ float4 sm4[];
    float4* wS = sm4;                 // [256][32]: e*32 + c4
    float4* vS = sm4 + 256*32;        // [32][64] : row*64 + e4

    int blk  = blockIdx.x;            // 0..129
    int t    = threadIdx.x;           // 0..255
    int row0 = blk * 32;

    const float4* W4 = (const float4*)Wout;
    #pragma unroll
    for (int i = t; i < 256*32; i += 256) wS[i] = W4[i];
    const float4* V4 = (const float4*)(g_vo + (size_t)row0*INNER_);
    #pragma unroll
    for (int i = t; i < 32*64; i += 256) vS[i] = V4[i];
    __syncthreads();

    int c4 = t & 31;                  // cols 4*c4 .. 4*c4+3
    int w  = t >> 5;                  // rows w, w+8, w+16, w+24
    float4 bo = ((const float4*)bout)[c4];
    float4 acc0 = bo, acc1 = bo, acc2 = bo, acc3 = bo;

    #pragma unroll 4
    for (int e4 = 0; e4 < 64; e4++) {
        float4 v0 = vS[(w     )*64 + e4];
        float4 v1 = vS[(w +  8)*64 + e4];
        float4 v2 = vS[(w + 16)*64 + e4];
        float4 v3 = vS[(w + 24)*64 + e4];
        #define OSTEP(KK, COMP)                                            \
        {   float4 wv = wS[(e4*4 + KK)*32 + c4];                           \
            acc0.x += v0.COMP*wv.x; acc0.y += v0.COMP*wv.y;                \
            acc0.z += v0.COMP*wv.z; acc0.w += v0.COMP*wv.w;                \
            acc1.x += v1.COMP*wv.x; acc1.y += v1.COMP*wv.y;                \
            acc1.z += v1.COMP*wv.z; acc1.w += v1.COMP*wv.w;                \
            acc2.x += v2.COMP*wv.x; acc2.y += v2.COMP*wv.y;                \
            acc2.z += v2.COMP*wv.z; acc2.w += v2.COMP*wv.w;                \
            acc3.x += v3.COMP*wv.x; acc3.y += v3.COMP*wv.y;                \
            acc3.z += v3.COMP*wv.z; acc3.w += v3.COMP*wv.w; }
        OSTEP(0, x) OSTEP(1, y) OSTEP(2, z) OSTEP(3, w)
        #undef OSTEP
    }

    ((float4*)(out + (size_t)(row0 + w     )*DIM_))[c4] = acc0;
    ((float4*)(out + (size_t)(row0 + w +  8)*DIM_))[c4] = acc1;
    ((float4*)(out + (size_t)(row0 + w + 16)*DIM_))[c4] = acc2;
    ((float4*)(out + (size_t)(row0 + w + 24)*DIM_))[c4] = acc3;
}

// ---------------- launch -----------------------------------------------------
extern "C" void kernel_launch(void* const* d_in, const int* in_sizes, int n_in,
                              void* d_out, int out_size) {
    const float* x     = (const float*)d_in[0];
    const float* gamma = (const float*)d_in[1];
    const float* beta  = (const float*)d_in[2];
    const float* Wqk   = (const float*)d_in[3];
    const float* Wv    = (const float*)d_in[4];
    const float* Wout  = (const float*)d_in[5];
    const float* bout  = (const float*)d_in[6];
    float* out = (float*)d_out;

    cudaFuncSetAttribute(vattn_kernel,
                         cudaFuncAttributeMaxDynamicSharedMemorySize,
                         K3_SMEM_BYTES);
    cudaFuncSetAttribute(out_kernel,
                         cudaFuncAttributeMaxDynamicSharedMemorySize,
                         K4_SMEM_BYTES);

    qkln_kernel<<<(B_*N_)/32, 256>>>(x, gamma, beta, Wqk);
    attn_kernel<<<B_*HEADS_, 256>>>();
    attn_tr_kernel<<<dim3((NM_ + 31)/32, BH_/32), 256>>>();
    dim3 g3(2, N_);
    vattn_kernel<<<g3, 256, K3_SMEM_BYTES>>>(Wv);
    out_kernel<<<(B_*N_)/32, 256, K4_SMEM_BYTES>>>(Wout, bout, out);
}